// round 7
// baseline (speedup 1.0000x reference)
#include <cuda_runtime.h>
#include <cuda_bf16.h>
#include <cuda_fp16.h>
#include <cstdint>

#define NN 50000
#define NE 1000000
#define DD 64
#define RR 8
#define ZC 512

// Scratch (allocation-free rule)
__device__ __half g_z[(size_t)NN * ZC];   // 51.2 MB fp16
__device__ uint32_t g_WfH[9 * 4 * 4 * 32 * 4];   // B fragments, hi (73728 B)
__device__ uint32_t g_WfL[9 * 4 * 4 * 32 * 4];   // B fragments, lo
__device__ int  g_cnt[NN];
__device__ int  g_rs[NN];       // scan result; advanced to segment END by fill
__device__ int  g_part[64];
__device__ int2 g_ep[NE];       // packed: {src*8+rel, w bits}

// ---------------------------------------------------------------------------
__device__ __forceinline__ uint32_t smem_u32(const void* p) {
    uint32_t a;
    asm("{ .reg .u64 t; cvta.to.shared.u64 t, %1; cvt.u32.u64 %0, t; }" : "=r"(a) : "l"(p));
    return a;
}
__device__ __forceinline__ void ldsm_x4(uint32_t* r, uint32_t addr) {
    asm volatile("ldmatrix.sync.aligned.m8n8.x4.shared.b16 {%0,%1,%2,%3}, [%4];"
                 : "=r"(r[0]), "=r"(r[1]), "=r"(r[2]), "=r"(r[3]) : "r"(addr));
}
__device__ __forceinline__ void mma_bf16(float* c, const uint32_t* a, uint32_t b0, uint32_t b1) {
    asm volatile("mma.sync.aligned.m16n8k16.row.col.f32.bf16.bf16.f32 "
                 "{%0,%1,%2,%3}, {%4,%5,%6,%7}, {%8,%9}, {%0,%1,%2,%3};"
                 : "+f"(c[0]), "+f"(c[1]), "+f"(c[2]), "+f"(c[3])
                 : "r"(a[0]), "r"(a[1]), "r"(a[2]), "r"(a[3]), "r"(b0), "r"(b1));
}
__device__ __forceinline__ int warp_iscan(int v, int lane) {
#pragma unroll
    for (int off = 1; off < 32; off <<= 1) {
        int t = __shfl_up_sync(0xFFFFFFFFu, v, off);
        if (lane >= off) v += t;
    }
    return v;
}

// ---------------------------------------------------------------------------
// Precompute B fragments in per-lane mma layout (hi/lo bf16 split).
// Index: (((g*4+kk)*4+q)*32+lane)*4 + c
//   nt = q*2 + (c>>1)  (n-tile 0..7),  b_sel = c&1  (b0/b1)
//   k  = kk*16 + (lane&3)*2 + b_sel*8,  j = nt*8 + (lane>>2)
//   value = bf16x2{ W[g*64+k][j], W[g*64+k+1][j] }
__global__ void prep_w_kernel(const float* __restrict__ Wlin, const float* __restrict__ Wself) {
    int i = blockIdx.x * blockDim.x + threadIdx.x;     // 18432
    if (i >= 9 * 4 * 4 * 32 * 4) return;
    int c = i & 3, lane = (i >> 2) & 31, q = (i >> 7) & 3, kk = (i >> 9) & 3, g = i >> 11;
    int nt = q * 2 + (c >> 1);
    int k  = kk * 16 + (lane & 3) * 2 + (c & 1) * 8;
    int j  = nt * 8 + (lane >> 2);
    float v0, v1;
    if (g < 8) { int row = g * 64 + k; v0 = Wlin[row * 64 + j]; v1 = Wlin[(row + 1) * 64 + j]; }
    else       { v0 = Wself[k * 64 + j]; v1 = Wself[(k + 1) * 64 + j]; }
    __nv_bfloat16 h0 = __float2bfloat16_rn(v0), h1 = __float2bfloat16_rn(v1);
    __nv_bfloat16 l0 = __float2bfloat16_rn(v0 - __bfloat162float(h0));
    __nv_bfloat16 l1 = __float2bfloat16_rn(v1 - __bfloat162float(h1));
    g_WfH[i] = (uint32_t)__bfloat16_as_ushort(h0) | ((uint32_t)__bfloat16_as_ushort(h1) << 16);
    g_WfL[i] = (uint32_t)__bfloat16_as_ushort(l0) | ((uint32_t)__bfloat16_as_ushort(l1) << 16);
}

// ---------------------------------------------------------------------------
// CSR build
__global__ void zero_cnt_kernel() {
    int i = blockIdx.x * blockDim.x + threadIdx.x;
    if (i < NN) g_cnt[i] = 0;
}
__global__ void hist_kernel(const int* __restrict__ dst) {
    int e = blockIdx.x * blockDim.x + threadIdx.x;
    if (e < NE) atomicAdd(&g_cnt[dst[e]], 1);
}
__global__ void scan1_kernel() {
    __shared__ int wsum[32];
    int tid = threadIdx.x, lane = tid & 31, wid = tid >> 5;
    int i = blockIdx.x * 1024 + tid;
    int v = (i < NN) ? g_cnt[i] : 0;
    int s = warp_iscan(v, lane);
    if (lane == 31) wsum[wid] = s;
    __syncthreads();
    if (wid == 0) {
        int t = wsum[lane];
        int sc = warp_iscan(t, lane);
        wsum[lane] = sc - t;
    }
    __syncthreads();
    int incl = s + wsum[wid];
    if (i < NN) g_rs[i] = incl - v;
    if (tid == 1023) g_part[blockIdx.x] = incl;
}
__global__ void scan2_kernel(int nblk) {
    __shared__ int w0tot;
    int tid = threadIdx.x, lane = tid & 31, wid = tid >> 5;
    int v = (tid < nblk) ? g_part[tid] : 0;
    int s = warp_iscan(v, lane);
    if (wid == 0 && lane == 31) w0tot = s;
    __syncthreads();
    if (wid == 1) s += w0tot;
    if (tid < nblk) g_part[tid] = s - v;
}
__global__ void scan3_kernel() {
    int tid = threadIdx.x;
    int i = blockIdx.x * 1024 + tid;
    if (i < NN) g_rs[i] += g_part[blockIdx.x];
}
__global__ void fill_kernel(const int* __restrict__ src, const int* __restrict__ dst,
                            const int* __restrict__ rel, const float* __restrict__ w) {
    int e = blockIdx.x * blockDim.x + threadIdx.x;
    if (e >= NE) return;
    int d = dst[e];
    int pos = atomicAdd(&g_rs[d], 1);
    g_ep[pos] = make_int2(src[e] * 8 + rel[e], __float_as_int(w[e]));
}

// ---------------------------------------------------------------------------
// GEMM: A staged in smem once; B fragments LDG'd from L1/L2-hot precomputed
// layout. Zero syncthreads in the main loop; warps fully independent.
#define AP 72
#define SM_BIAS 0
#define SM_AH   256
#define SM_AL   (SM_AH + 128 * AP * 2)
#define SMEM_TOTAL (SM_AL + 128 * AP * 2)   // 37120 B

__global__ __launch_bounds__(256) void gemm_kernel(const float* __restrict__ x,
                                                   const float* __restrict__ b_lin,
                                                   const float* __restrict__ b_self,
                                                   float* __restrict__ out) {
    extern __shared__ char smem[];
    uint32_t sb = smem_u32(smem);
    int t = threadIdx.x, wid = t >> 5, lid = t & 31;
    int m_base = blockIdx.x * 128;

    float* bias = (float*)(smem + SM_BIAS);
    if (t < 64) bias[t] = b_lin[t] + b_self[t];

    // Stage A: 128x64 fp32 -> hi/lo bf16 (padded rows, conflict-free ldmatrix)
    for (int f = t; f < 128 * 32; f += 256) {
        int m = f >> 5, kp = f & 31;
        float2 v = make_float2(0.f, 0.f);
        int gm = m_base + m;
        if (gm < NN) v = *(const float2*)&x[gm * DD + kp * 2];
        __nv_bfloat16 hx = __float2bfloat16_rn(v.x);
        __nv_bfloat16 hy = __float2bfloat16_rn(v.y);
        __nv_bfloat16 lx = __float2bfloat16_rn(v.x - __bfloat162float(hx));
        __nv_bfloat16 ly = __float2bfloat16_rn(v.y - __bfloat162float(hy));
        uint32_t hp = (uint32_t)__bfloat16_as_ushort(hx) | ((uint32_t)__bfloat16_as_ushort(hy) << 16);
        uint32_t lp = (uint32_t)__bfloat16_as_ushort(lx) | ((uint32_t)__bfloat16_as_ushort(ly) << 16);
        uint32_t boff = (uint32_t)(m * AP + kp * 2) * 2;
        *(uint32_t*)(smem + SM_AH + boff) = hp;
        *(uint32_t*)(smem + SM_AL + boff) = lp;
    }
    __syncthreads();

    // A fragments (persist across all 9 tiles)
    uint32_t a_h[4][4], a_l[4][4];
    {
        int arow = wid * 16 + (lid & 7) + ((lid >> 3) & 1) * 8;
        int acol = (lid >> 4) * 8;
#pragma unroll
        for (int kk = 0; kk < 4; kk++) {
            uint32_t off = (uint32_t)(arow * AP + kk * 16 + acol) * 2;
            ldsm_x4(a_h[kk], sb + SM_AH + off);
            ldsm_x4(a_l[kk], sb + SM_AL + off);
        }
    }

    const uint4* WfH = (const uint4*)g_WfH;   // index ((g*4+kk)*4+q)*32 + lane
    const uint4* WfL = (const uint4*)g_WfL;

    for (int g = 0; g < 9; g++) {
        float acc[8][4];
#pragma unroll
        for (int n = 0; n < 8; n++)
#pragma unroll
            for (int q = 0; q < 4; q++) acc[n][q] = 0.f;

#pragma unroll
        for (int kk = 0; kk < 4; kk++) {
            uint4 bh[4], bl[4];
#pragma unroll
            for (int q = 0; q < 4; q++) {
                int idx = ((g * 4 + kk) * 4 + q) * 32 + lid;
                bh[q] = WfH[idx];
                bl[q] = WfL[idx];
            }
#pragma unroll
            for (int n = 0; n < 8; n++) {
                uint32_t b0h = (n & 1) ? bh[n >> 1].z : bh[n >> 1].x;
                uint32_t b1h = (n & 1) ? bh[n >> 1].w : bh[n >> 1].y;
                uint32_t b0l = (n & 1) ? bl[n >> 1].z : bl[n >> 1].x;
                uint32_t b1l = (n & 1) ? bl[n >> 1].w : bl[n >> 1].y;
                mma_bf16(acc[n], a_h[kk], b0h, b1h);
                mma_bf16(acc[n], a_h[kk], b0l, b1l);
                mma_bf16(acc[n], a_l[kk], b0h, b1h);
            }
        }

        int r0 = m_base + wid * 16 + (lid >> 2);
        int r1 = r0 + 8;
        int c0 = (lid & 3) * 2;
        if (g < 8) {
#pragma unroll
            for (int n = 0; n < 8; n++) {
                int col = g * 64 + n * 8 + c0;
                __half2 v0 = __float22half2_rn(make_float2(acc[n][0], acc[n][1]));
                __half2 v1 = __float22half2_rn(make_float2(acc[n][2], acc[n][3]));
                if (r0 < NN) *(__half2*)&g_z[(size_t)r0 * ZC + col] = v0;
                if (r1 < NN) *(__half2*)&g_z[(size_t)r1 * ZC + col] = v1;
            }
        } else {
#pragma unroll
            for (int n = 0; n < 8; n++) {
                int col = n * 8 + c0;
                float2 bs = *(float2*)&bias[col];
                if (r0 < NN) *(float2*)&out[r0 * DD + col] = make_float2(acc[n][0] + bs.x, acc[n][1] + bs.y);
                if (r1 < NN) *(float2*)&out[r1 * DD + col] = make_float2(acc[n][2] + bs.x, acc[n][3] + bs.y);
            }
        }
    }
}

// ---------------------------------------------------------------------------
// Gather: one warp per destination node; z rows fp16 (128 B). Unroll x4.
__global__ __launch_bounds__(256) void gather_kernel(float* __restrict__ out) {
    __shared__ float sinv[8][8];
    int t = threadIdx.x, wid = t >> 5, lid = t & 31;
    int node = blockIdx.x * 8 + wid;
    int end = g_rs[node];                 // post-fill: segment end
    int beg = end - g_cnt[node];

    float deg8[8];
#pragma unroll
    for (int q = 0; q < 8; q++) deg8[q] = 0.f;
    for (int i = beg + lid; i < end; i += 32) {
        int2 p = g_ep[i];
        int r = p.x & 7;
        float w = __int_as_float(p.y);
#pragma unroll
        for (int q = 0; q < 8; q++) if (r == q) deg8[q] += w;
    }
#pragma unroll
    for (int q = 0; q < 8; q++)
#pragma unroll
        for (int o = 16; o; o >>= 1) deg8[q] += __shfl_xor_sync(0xFFFFFFFFu, deg8[q], o);
    if (lid == 0) {
#pragma unroll
        for (int q = 0; q < 8; q++) sinv[wid][q] = 1.0f / deg8[q];
    }
    __syncwarp();

    float a0 = 0.f, a1 = 0.f;
    int i = beg;
    for (; i + 3 < end; i += 4) {
        int2 p0 = g_ep[i], p1 = g_ep[i + 1], p2 = g_ep[i + 2], p3 = g_ep[i + 3];
        __half2 zb0 = *(const __half2*)&g_z[(size_t)p0.x * 64 + lid * 2];
        __half2 zb1 = *(const __half2*)&g_z[(size_t)p1.x * 64 + lid * 2];
        __half2 zb2 = *(const __half2*)&g_z[(size_t)p2.x * 64 + lid * 2];
        __half2 zb3 = *(const __half2*)&g_z[(size_t)p3.x * 64 + lid * 2];
        float v0 = __int_as_float(p0.y) * sinv[wid][p0.x & 7];
        float v1 = __int_as_float(p1.y) * sinv[wid][p1.x & 7];
        float v2 = __int_as_float(p2.y) * sinv[wid][p2.x & 7];
        float v3 = __int_as_float(p3.y) * sinv[wid][p3.x & 7];
        float2 z0 = __half22float2(zb0);
        float2 z1 = __half22float2(zb1);
        float2 z2 = __half22float2(zb2);
        float2 z3 = __half22float2(zb3);
        a0 += v0 * z0.x + v1 * z1.x + v2 * z2.x + v3 * z3.x;
        a1 += v0 * z0.y + v1 * z1.y + v2 * z2.y + v3 * z3.y;
    }
    for (; i < end; i++) {
        int2 p0 = g_ep[i];
        __half2 zb0 = *(const __half2*)&g_z[(size_t)p0.x * 64 + lid * 2];
        float v0 = __int_as_float(p0.y) * sinv[wid][p0.x & 7];
        float2 z0 = __half22float2(zb0);
        a0 += v0 * z0.x;
        a1 += v0 * z0.y;
    }

    float2 o = *(float2*)&out[node * DD + lid * 2];
    o.x = fmaxf(o.x + a0, 0.f);
    o.y = fmaxf(o.y + a1, 0.f);
    *(float2*)&out[node * DD + lid * 2] = o;
}

// ---------------------------------------------------------------------------
extern "C" void kernel_launch(void* const* d_in, const int* in_sizes, int n_in,
                              void* d_out, int out_size) {
    const float* x      = (const float*)d_in[0];
    const int*   e_src  = (const int*)d_in[1];
    const int*   e_dst  = (const int*)d_in[2];
    const int*   e_rel  = (const int*)d_in[3];
    const float* e_w    = (const float*)d_in[4];
    const float* W_lin  = (const float*)d_in[5];
    const float* b_lin  = (const float*)d_in[6];
    const float* W_self = (const float*)d_in[7];
    const float* b_self = (const float*)d_in[8];
    float* out = (float*)d_out;

    cudaFuncSetAttribute(gemm_kernel, cudaFuncAttributeMaxDynamicSharedMemorySize, SMEM_TOTAL);

    const int SCAN_BLKS = (NN + 1023) / 1024;   // 49
    zero_cnt_kernel<<<(NN + 255) / 256, 256>>>();
    hist_kernel<<<(NE + 255) / 256, 256>>>(e_dst);
    prep_w_kernel<<<(18432 + 255) / 256, 256>>>(W_lin, W_self);
    gemm_kernel<<<(NN + 127) / 128, 256, SMEM_TOTAL>>>(x, b_lin, b_self, out);
    scan1_kernel<<<SCAN_BLKS, 1024>>>();
    scan2_kernel<<<1, 64>>>(SCAN_BLKS);
    scan3_kernel<<<SCAN_BLKS, 1024>>>();
    fill_kernel<<<(NE + 255) / 256, 256>>>(e_src, e_dst, e_rel, e_w);
    gather_kernel<<<NN / 8, 256>>>(out);
}

// round 8
// speedup vs baseline: 1.3078x; 1.3078x over previous
#include <cuda_runtime.h>
#include <cuda_fp16.h>
#include <cstdint>

#define NN 50000
#define NE 1000000
#define DD 64
#define RR 8
#define ZC 512

// Scratch (allocation-free rule)
__device__ __half g_z[(size_t)NN * ZC];        // 51.2 MB fp16
__device__ uint32_t g_Wf[9 * 4 * 4 * 32 * 4];  // fp16 B fragments (73728 B)
__device__ int  g_cnt[NN];
__device__ int  g_rs[NN];       // scan result; advanced to segment END by fill
__device__ int  g_part[64];
__device__ int2 g_ep[NE];       // packed: {src*8+rel, w bits}

// ---------------------------------------------------------------------------
__device__ __forceinline__ uint32_t smem_u32(const void* p) {
    uint32_t a;
    asm("{ .reg .u64 t; cvta.to.shared.u64 t, %1; cvt.u32.u64 %0, t; }" : "=r"(a) : "l"(p));
    return a;
}
__device__ __forceinline__ void ldsm_x4(uint32_t* r, uint32_t addr) {
    asm volatile("ldmatrix.sync.aligned.m8n8.x4.shared.b16 {%0,%1,%2,%3}, [%4];"
                 : "=r"(r[0]), "=r"(r[1]), "=r"(r[2]), "=r"(r[3]) : "r"(addr));
}
__device__ __forceinline__ void mma_f16(float* c, const uint32_t* a, uint32_t b0, uint32_t b1) {
    asm volatile("mma.sync.aligned.m16n8k16.row.col.f32.f16.f16.f32 "
                 "{%0,%1,%2,%3}, {%4,%5,%6,%7}, {%8,%9}, {%0,%1,%2,%3};"
                 : "+f"(c[0]), "+f"(c[1]), "+f"(c[2]), "+f"(c[3])
                 : "r"(a[0]), "r"(a[1]), "r"(a[2]), "r"(a[3]), "r"(b0), "r"(b1));
}
__device__ __forceinline__ int warp_iscan(int v, int lane) {
#pragma unroll
    for (int off = 1; off < 32; off <<= 1) {
        int t = __shfl_up_sync(0xFFFFFFFFu, v, off);
        if (lane >= off) v += t;
    }
    return v;
}

// ---------------------------------------------------------------------------
// Precompute B fragments in per-lane mma layout (fp16).
// Index: (((g*4+kk)*4+q)*32+lane)*4 + c
//   nt = q*2 + (c>>1), b_sel = c&1
//   k  = kk*16 + (lane&3)*2 + b_sel*8,  j = nt*8 + (lane>>2)
//   value = half2{ W[g*64+k][j], W[g*64+k+1][j] }
__global__ void prep_w_kernel(const float* __restrict__ Wlin, const float* __restrict__ Wself) {
    int i = blockIdx.x * blockDim.x + threadIdx.x;     // 18432
    if (i >= 9 * 4 * 4 * 32 * 4) return;
    int c = i & 3, lane = (i >> 2) & 31, q = (i >> 7) & 3, kk = (i >> 9) & 3, g = i >> 11;
    int nt = q * 2 + (c >> 1);
    int k  = kk * 16 + (lane & 3) * 2 + (c & 1) * 8;
    int j  = nt * 8 + (lane >> 2);
    float v0, v1;
    if (g < 8) { int row = g * 64 + k; v0 = Wlin[row * 64 + j]; v1 = Wlin[(row + 1) * 64 + j]; }
    else       { v0 = Wself[k * 64 + j]; v1 = Wself[(k + 1) * 64 + j]; }
    __half h0 = __float2half_rn(v0), h1 = __float2half_rn(v1);
    g_Wf[i] = (uint32_t)__half_as_ushort(h0) | ((uint32_t)__half_as_ushort(h1) << 16);
}

// ---------------------------------------------------------------------------
// CSR build
__global__ void zero_cnt_kernel() {
    int i = blockIdx.x * blockDim.x + threadIdx.x;
    if (i < NN) g_cnt[i] = 0;
}
__global__ void hist_kernel(const int* __restrict__ dst) {
    int e = blockIdx.x * blockDim.x + threadIdx.x;
    if (e < NE) atomicAdd(&g_cnt[dst[e]], 1);
}
__global__ void scan1_kernel() {
    __shared__ int wsum[32];
    int tid = threadIdx.x, lane = tid & 31, wid = tid >> 5;
    int i = blockIdx.x * 1024 + tid;
    int v = (i < NN) ? g_cnt[i] : 0;
    int s = warp_iscan(v, lane);
    if (lane == 31) wsum[wid] = s;
    __syncthreads();
    if (wid == 0) {
        int t = wsum[lane];
        int sc = warp_iscan(t, lane);
        wsum[lane] = sc - t;
    }
    __syncthreads();
    int incl = s + wsum[wid];
    if (i < NN) g_rs[i] = incl - v;
    if (tid == 1023) g_part[blockIdx.x] = incl;
}
__global__ void scan2_kernel(int nblk) {
    __shared__ int w0tot;
    int tid = threadIdx.x, lane = tid & 31, wid = tid >> 5;
    int v = (tid < nblk) ? g_part[tid] : 0;
    int s = warp_iscan(v, lane);
    if (wid == 0 && lane == 31) w0tot = s;
    __syncthreads();
    if (wid == 1) s += w0tot;
    if (tid < nblk) g_part[tid] = s - v;
}
__global__ void scan3_kernel() {
    int tid = threadIdx.x;
    int i = blockIdx.x * 1024 + tid;
    if (i < NN) g_rs[i] += g_part[blockIdx.x];
}
__global__ void fill_kernel(const int* __restrict__ src, const int* __restrict__ dst,
                            const int* __restrict__ rel, const float* __restrict__ w) {
    int e = blockIdx.x * blockDim.x + threadIdx.x;
    if (e >= NE) return;
    int d = dst[e];
    int pos = atomicAdd(&g_rs[d], 1);
    g_ep[pos] = make_int2(src[e] * 8 + rel[e], __float_as_int(w[e]));
}

// ---------------------------------------------------------------------------
// GEMM: A staged in smem once (fp16); B fragments LDG'd from L1-hot
// precomputed layout; single fp16 MMA per term; no syncs in main loop.
#define AP 72
#define SM_BIAS 0
#define SM_AH   256
#define SMEM_TOTAL (SM_AH + 128 * AP * 2)   // 18688 B

__global__ __launch_bounds__(256) void gemm_kernel(const float* __restrict__ x,
                                                   const float* __restrict__ b_lin,
                                                   const float* __restrict__ b_self,
                                                   float* __restrict__ out) {
    extern __shared__ char smem[];
    uint32_t sb = smem_u32(smem);
    int t = threadIdx.x, wid = t >> 5, lid = t & 31;
    int m_base = blockIdx.x * 128;

    float* bias = (float*)(smem + SM_BIAS);
    if (t < 64) bias[t] = b_lin[t] + b_self[t];

    // Stage A: 128x64 fp32 -> fp16 (padded rows, conflict-free ldmatrix)
    for (int f = t; f < 128 * 32; f += 256) {
        int m = f >> 5, kp = f & 31;
        float2 v = make_float2(0.f, 0.f);
        int gm = m_base + m;
        if (gm < NN) v = *(const float2*)&x[gm * DD + kp * 2];
        __half2 h = __float22half2_rn(v);
        *(__half2*)(smem + SM_AH + (uint32_t)(m * AP + kp * 2) * 2) = h;
    }
    __syncthreads();

    // A fragments (persist across all 9 tiles)
    uint32_t a[4][4];
    {
        int arow = wid * 16 + (lid & 7) + ((lid >> 3) & 1) * 8;
        int acol = (lid >> 4) * 8;
#pragma unroll
        for (int kk = 0; kk < 4; kk++)
            ldsm_x4(a[kk], sb + SM_AH + (uint32_t)(arow * AP + kk * 16 + acol) * 2);
    }

    const uint4* Wf = (const uint4*)g_Wf;   // index ((g*4+kk)*4+q)*32 + lane

    for (int g = 0; g < 9; g++) {
        float acc[8][4];
#pragma unroll
        for (int n = 0; n < 8; n++)
#pragma unroll
            for (int q = 0; q < 4; q++) acc[n][q] = 0.f;

#pragma unroll
        for (int kk = 0; kk < 4; kk++) {
            uint4 b[4];
#pragma unroll
            for (int q = 0; q < 4; q++)
                b[q] = Wf[((g * 4 + kk) * 4 + q) * 32 + lid];
#pragma unroll
            for (int n = 0; n < 8; n++) {
                uint32_t b0 = (n & 1) ? b[n >> 1].z : b[n >> 1].x;
                uint32_t b1 = (n & 1) ? b[n >> 1].w : b[n >> 1].y;
                mma_f16(acc[n], a[kk], b0, b1);
            }
        }

        int r0 = m_base + wid * 16 + (lid >> 2);
        int r1 = r0 + 8;
        int c0 = (lid & 3) * 2;
        if (g < 8) {
#pragma unroll
            for (int n = 0; n < 8; n++) {
                int col = g * 64 + n * 8 + c0;
                __half2 v0 = __float22half2_rn(make_float2(acc[n][0], acc[n][1]));
                __half2 v1 = __float22half2_rn(make_float2(acc[n][2], acc[n][3]));
                if (r0 < NN) *(__half2*)&g_z[(size_t)r0 * ZC + col] = v0;
                if (r1 < NN) *(__half2*)&g_z[(size_t)r1 * ZC + col] = v1;
            }
        } else {
#pragma unroll
            for (int n = 0; n < 8; n++) {
                int col = n * 8 + c0;
                float2 bs = *(float2*)&bias[col];
                if (r0 < NN) *(float2*)&out[r0 * DD + col] = make_float2(acc[n][0] + bs.x, acc[n][1] + bs.y);
                if (r1 < NN) *(float2*)&out[r1 * DD + col] = make_float2(acc[n][2] + bs.x, acc[n][3] + bs.y);
            }
        }
    }
}

// ---------------------------------------------------------------------------
// Gather: one warp per destination node; z rows fp16 (128 B). Unroll x4.
__global__ __launch_bounds__(256) void gather_kernel(float* __restrict__ out) {
    __shared__ float sinv[8][8];
    int t = threadIdx.x, wid = t >> 5, lid = t & 31;
    int node = blockIdx.x * 8 + wid;
    int end = g_rs[node];                 // post-fill: segment end
    int beg = end - g_cnt[node];

    float deg8[8];
#pragma unroll
    for (int q = 0; q < 8; q++) deg8[q] = 0.f;
    for (int i = beg + lid; i < end; i += 32) {
        int2 p = g_ep[i];
        int r = p.x & 7;
        float w = __int_as_float(p.y);
#pragma unroll
        for (int q = 0; q < 8; q++) if (r == q) deg8[q] += w;
    }
#pragma unroll
    for (int q = 0; q < 8; q++)
#pragma unroll
        for (int o = 16; o; o >>= 1) deg8[q] += __shfl_xor_sync(0xFFFFFFFFu, deg8[q], o);
    if (lid == 0) {
#pragma unroll
        for (int q = 0; q < 8; q++) sinv[wid][q] = 1.0f / deg8[q];
    }
    __syncwarp();

    float a0 = 0.f, a1 = 0.f;
    int i = beg;
    for (; i + 3 < end; i += 4) {
        int2 p0 = g_ep[i], p1 = g_ep[i + 1], p2 = g_ep[i + 2], p3 = g_ep[i + 3];
        __half2 zb0 = *(const __half2*)&g_z[(size_t)p0.x * 64 + lid * 2];
        __half2 zb1 = *(const __half2*)&g_z[(size_t)p1.x * 64 + lid * 2];
        __half2 zb2 = *(const __half2*)&g_z[(size_t)p2.x * 64 + lid * 2];
        __half2 zb3 = *(const __half2*)&g_z[(size_t)p3.x * 64 + lid * 2];
        float v0 = __int_as_float(p0.y) * sinv[wid][p0.x & 7];
        float v1 = __int_as_float(p1.y) * sinv[wid][p1.x & 7];
        float v2 = __int_as_float(p2.y) * sinv[wid][p2.x & 7];
        float v3 = __int_as_float(p3.y) * sinv[wid][p3.x & 7];
        float2 z0 = __half22float2(zb0);
        float2 z1 = __half22float2(zb1);
        float2 z2 = __half22float2(zb2);
        float2 z3 = __half22float2(zb3);
        a0 += v0 * z0.x + v1 * z1.x + v2 * z2.x + v3 * z3.x;
        a1 += v0 * z0.y + v1 * z1.y + v2 * z2.y + v3 * z3.y;
    }
    for (; i < end; i++) {
        int2 p0 = g_ep[i];
        __half2 zb0 = *(const __half2*)&g_z[(size_t)p0.x * 64 + lid * 2];
        float v0 = __int_as_float(p0.y) * sinv[wid][p0.x & 7];
        float2 z0 = __half22float2(zb0);
        a0 += v0 * z0.x;
        a1 += v0 * z0.y;
    }

    float2 o = *(float2*)&out[node * DD + lid * 2];
    o.x = fmaxf(o.x + a0, 0.f);
    o.y = fmaxf(o.y + a1, 0.f);
    *(float2*)&out[node * DD + lid * 2] = o;
}

// ---------------------------------------------------------------------------
extern "C" void kernel_launch(void* const* d_in, const int* in_sizes, int n_in,
                              void* d_out, int out_size) {
    const float* x      = (const float*)d_in[0];
    const int*   e_src  = (const int*)d_in[1];
    const int*   e_dst  = (const int*)d_in[2];
    const int*   e_rel  = (const int*)d_in[3];
    const float* e_w    = (const float*)d_in[4];
    const float* W_lin  = (const float*)d_in[5];
    const float* b_lin  = (const float*)d_in[6];
    const float* W_self = (const float*)d_in[7];
    const float* b_self = (const float*)d_in[8];
    float* out = (float*)d_out;

    cudaFuncSetAttribute(gemm_kernel, cudaFuncAttributeMaxDynamicSharedMemorySize, SMEM_TOTAL);

    const int SCAN_BLKS = (NN + 1023) / 1024;   // 49
    zero_cnt_kernel<<<(NN + 255) / 256, 256>>>();
    hist_kernel<<<(NE + 255) / 256, 256>>>(e_dst);
    prep_w_kernel<<<(18432 + 255) / 256, 256>>>(W_lin, W_self);
    gemm_kernel<<<(NN + 127) / 128, 256, SMEM_TOTAL>>>(x, b_lin, b_self, out);
    scan1_kernel<<<SCAN_BLKS, 1024>>>();
    scan2_kernel<<<1, 64>>>(SCAN_BLKS);
    scan3_kernel<<<SCAN_BLKS, 1024>>>();
    fill_kernel<<<(NE + 255) / 256, 256>>>(e_src, e_dst, e_rel, e_w);
    gather_kernel<<<NN / 8, 256>>>(out);
}

// round 9
// speedup vs baseline: 1.6041x; 1.2266x over previous
#include <cuda_runtime.h>
#include <cuda_fp16.h>
#include <cstdint>

#define NN 50000
#define NE 1000000
#define DD 64
#define RR 8
#define ZC 512

// Scratch (allocation-free rule)
__device__ __half g_z[(size_t)NN * ZC];        // 51.2 MB fp16
__device__ uint32_t g_Wf[9 * 4 * 4 * 32 * 4];  // fp16 B fragments (73728 B)
__device__ int  g_cnt[NN];
__device__ int  g_rs[NN];       // scan result; advanced to segment END by fill
__device__ int  g_part[64];
__device__ int2 g_ep[NE];       // packed: {src*8+rel, w bits}

// ---------------------------------------------------------------------------
__device__ __forceinline__ uint32_t smem_u32(const void* p) {
    uint32_t a;
    asm("{ .reg .u64 t; cvta.to.shared.u64 t, %1; cvt.u32.u64 %0, t; }" : "=r"(a) : "l"(p));
    return a;
}
__device__ __forceinline__ void ldsm_x4(uint32_t* r, uint32_t addr) {
    asm volatile("ldmatrix.sync.aligned.m8n8.x4.shared.b16 {%0,%1,%2,%3}, [%4];"
                 : "=r"(r[0]), "=r"(r[1]), "=r"(r[2]), "=r"(r[3]) : "r"(addr));
}
__device__ __forceinline__ void mma_f16(float* c, const uint32_t* a, uint32_t b0, uint32_t b1) {
    asm volatile("mma.sync.aligned.m16n8k16.row.col.f32.f16.f16.f32 "
                 "{%0,%1,%2,%3}, {%4,%5,%6,%7}, {%8,%9}, {%0,%1,%2,%3};"
                 : "+f"(c[0]), "+f"(c[1]), "+f"(c[2]), "+f"(c[3])
                 : "r"(a[0]), "r"(a[1]), "r"(a[2]), "r"(a[3]), "r"(b0), "r"(b1));
}
__device__ __forceinline__ int warp_iscan(int v, int lane) {
#pragma unroll
    for (int off = 1; off < 32; off <<= 1) {
        int t = __shfl_up_sync(0xFFFFFFFFu, v, off);
        if (lane >= off) v += t;
    }
    return v;
}

// ---------------------------------------------------------------------------
// B fragments in per-lane mma layout (fp16).
__global__ void prep_w_kernel(const float* __restrict__ Wlin, const float* __restrict__ Wself) {
    int i = blockIdx.x * blockDim.x + threadIdx.x;     // 18432
    if (i >= 9 * 4 * 4 * 32 * 4) return;
    int c = i & 3, lane = (i >> 2) & 31, q = (i >> 7) & 3, kk = (i >> 9) & 3, g = i >> 11;
    int nt = q * 2 + (c >> 1);
    int k  = kk * 16 + (lane & 3) * 2 + (c & 1) * 8;
    int j  = nt * 8 + (lane >> 2);
    float v0, v1;
    if (g < 8) { int row = g * 64 + k; v0 = Wlin[row * 64 + j]; v1 = Wlin[(row + 1) * 64 + j]; }
    else       { v0 = Wself[k * 64 + j]; v1 = Wself[(k + 1) * 64 + j]; }
    __half h0 = __float2half_rn(v0), h1 = __float2half_rn(v1);
    g_Wf[i] = (uint32_t)__half_as_ushort(h0) | ((uint32_t)__half_as_ushort(h1) << 16);
}

// ---------------------------------------------------------------------------
// CSR build
__global__ void zero_cnt_kernel() {
    int i = blockIdx.x * blockDim.x + threadIdx.x;
    if (i < NN) g_cnt[i] = 0;
}
__global__ void hist_kernel(const int* __restrict__ dst) {
    int e = blockIdx.x * blockDim.x + threadIdx.x;
    if (e < NE) atomicAdd(&g_cnt[dst[e]], 1);
}
__global__ void scan1_kernel() {
    __shared__ int wsum[32];
    int tid = threadIdx.x, lane = tid & 31, wid = tid >> 5;
    int i = blockIdx.x * 1024 + tid;
    int v = (i < NN) ? g_cnt[i] : 0;
    int s = warp_iscan(v, lane);
    if (lane == 31) wsum[wid] = s;
    __syncthreads();
    if (wid == 0) {
        int t = wsum[lane];
        int sc = warp_iscan(t, lane);
        wsum[lane] = sc - t;
    }
    __syncthreads();
    int incl = s + wsum[wid];
    if (i < NN) g_rs[i] = incl - v;
    if (tid == 1023) g_part[blockIdx.x] = incl;
}
__global__ void scan2_kernel(int nblk) {
    __shared__ int w0tot;
    int tid = threadIdx.x, lane = tid & 31, wid = tid >> 5;
    int v = (tid < nblk) ? g_part[tid] : 0;
    int s = warp_iscan(v, lane);
    if (wid == 0 && lane == 31) w0tot = s;
    __syncthreads();
    if (wid == 1) s += w0tot;
    if (tid < nblk) g_part[tid] = s - v;
}
__global__ void scan3_kernel() {
    int tid = threadIdx.x;
    int i = blockIdx.x * 1024 + tid;
    if (i < NN) g_rs[i] += g_part[blockIdx.x];
}
__global__ void fill_kernel(const int* __restrict__ src, const int* __restrict__ dst,
                            const int* __restrict__ rel, const float* __restrict__ w) {
    int e = blockIdx.x * blockDim.x + threadIdx.x;
    if (e >= NE) return;
    int d = dst[e];
    int pos = atomicAdd(&g_rs[d], 1);
    g_ep[pos] = make_int2(src[e] * 8 + rel[e], __float_as_int(w[e]));
}

// ---------------------------------------------------------------------------
// GEMM: A staged in smem (fp16), fragments persist in regs; B from L1-hot
// precomputed fragments. z writeout staged through smem for full coalescing.
#define AP 72
#define SM_BIAS 0
#define SM_AH   256                           // reused as z staging after ldsm
#define SMEM_TOTAL (SM_AH + 128 * AP * 2)     // 18688 B

__global__ __launch_bounds__(256) void gemm_kernel(const float* __restrict__ x,
                                                   const float* __restrict__ b_lin,
                                                   const float* __restrict__ b_self,
                                                   float* __restrict__ out) {
    extern __shared__ char smem[];
    uint32_t sb = smem_u32(smem);
    int t = threadIdx.x, wid = t >> 5, lid = t & 31;
    int m_base = blockIdx.x * 128;

    float* bias = (float*)(smem + SM_BIAS);
    if (t < 64) bias[t] = b_lin[t] + b_self[t];

    // Stage A: 128x64 fp32 -> fp16 (stride-72 rows: conflict-free ldmatrix)
    for (int f = t; f < 128 * 32; f += 256) {
        int m = f >> 5, kp = f & 31;
        float2 v = make_float2(0.f, 0.f);
        int gm = m_base + m;
        if (gm < NN) v = *(const float2*)&x[gm * DD + kp * 2];
        *(__half2*)(smem + SM_AH + (uint32_t)(m * AP + kp * 2) * 2) = __float22half2_rn(v);
    }
    __syncthreads();

    // A fragments (persist across all 9 tiles). Each warp reads only its 16 rows.
    uint32_t a[4][4];
    {
        int arow = wid * 16 + (lid & 7) + ((lid >> 3) & 1) * 8;
        int acol = (lid >> 4) * 8;
#pragma unroll
        for (int kk = 0; kk < 4; kk++)
            ldsm_x4(a[kk], sb + SM_AH + (uint32_t)(arow * AP + kk * 16 + acol) * 2);
    }

    const uint4* Wf = (const uint4*)g_Wf;
    __half* zst = (__half*)(smem + SM_AH);    // staging tile [128][64], stride AP

    for (int g = 0; g < 9; g++) {
        float acc[8][4];
#pragma unroll
        for (int n = 0; n < 8; n++)
#pragma unroll
            for (int q = 0; q < 4; q++) acc[n][q] = 0.f;

#pragma unroll
        for (int kk = 0; kk < 4; kk++) {
            uint4 b[4];
#pragma unroll
            for (int q = 0; q < 4; q++)
                b[q] = Wf[((g * 4 + kk) * 4 + q) * 32 + lid];
#pragma unroll
            for (int n = 0; n < 8; n++) {
                uint32_t b0 = (n & 1) ? b[n >> 1].z : b[n >> 1].x;
                uint32_t b1 = (n & 1) ? b[n >> 1].w : b[n >> 1].y;
                mma_f16(acc[n], a[kk], b0, b1);
            }
        }

        int rr0 = wid * 16 + (lid >> 2);       // local rows
        int rr1 = rr0 + 8;
        int c0 = (lid & 3) * 2;
        if (g < 8) {
            __syncthreads();                   // prior copy done (g=0: ldsm done)
#pragma unroll
            for (int n = 0; n < 8; n++) {
                int col = n * 8 + c0;
                *(__half2*)&zst[rr0 * AP + col] = __float22half2_rn(make_float2(acc[n][0], acc[n][1]));
                *(__half2*)&zst[rr1 * AP + col] = __float22half2_rn(make_float2(acc[n][2], acc[n][3]));
            }
            __syncthreads();
            // coalesced copy: 128 rows x 8 chunks of 16B; 8 threads per row
            for (int f = t; f < 128 * 8; f += 256) {
                int row = f >> 3, ch = f & 7;
                int gm = m_base + row;
                if (gm < NN) {
                    uint4 v = *(const uint4*)&zst[row * AP + ch * 8];
                    *(uint4*)&g_z[(size_t)gm * ZC + g * 64 + ch * 8] = v;
                }
            }
        } else {
            int r0 = m_base + rr0, r1 = m_base + rr1;
#pragma unroll
            for (int n = 0; n < 8; n++) {
                int col = n * 8 + c0;
                float2 bs = *(float2*)&bias[col];
                if (r0 < NN) *(float2*)&out[r0 * DD + col] = make_float2(acc[n][0] + bs.x, acc[n][1] + bs.y);
                if (r1 < NN) *(float2*)&out[r1 * DD + col] = make_float2(acc[n][2] + bs.x, acc[n][3] + bs.y);
            }
        }
    }
}

// ---------------------------------------------------------------------------
// Gather: one warp per destination node; z rows fp16 (128 B). Unroll x4.
__global__ __launch_bounds__(256) void gather_kernel(float* __restrict__ out) {
    __shared__ float sinv[8][8];
    int t = threadIdx.x, wid = t >> 5, lid = t & 31;
    int node = blockIdx.x * 8 + wid;
    int end = g_rs[node];                 // post-fill: segment end
    int beg = end - g_cnt[node];

    float deg8[8];
#pragma unroll
    for (int q = 0; q < 8; q++) deg8[q] = 0.f;
    for (int i = beg + lid; i < end; i += 32) {
        int2 p = g_ep[i];
        int r = p.x & 7;
        float w = __int_as_float(p.y);
#pragma unroll
        for (int q = 0; q < 8; q++) if (r == q) deg8[q] += w;
    }
#pragma unroll
    for (int q = 0; q < 8; q++)
#pragma unroll
        for (int o = 16; o; o >>= 1) deg8[q] += __shfl_xor_sync(0xFFFFFFFFu, deg8[q], o);
    if (lid == 0) {
#pragma unroll
        for (int q = 0; q < 8; q++) sinv[wid][q] = 1.0f / deg8[q];
    }
    __syncwarp();

    float a0 = 0.f, a1 = 0.f;
    int i = beg;
    for (; i + 3 < end; i += 4) {
        int2 p0 = g_ep[i], p1 = g_ep[i + 1], p2 = g_ep[i + 2], p3 = g_ep[i + 3];
        __half2 zb0 = *(const __half2*)&g_z[(size_t)p0.x * 64 + lid * 2];
        __half2 zb1 = *(const __half2*)&g_z[(size_t)p1.x * 64 + lid * 2];
        __half2 zb2 = *(const __half2*)&g_z[(size_t)p2.x * 64 + lid * 2];
        __half2 zb3 = *(const __half2*)&g_z[(size_t)p3.x * 64 + lid * 2];
        float v0 = __int_as_float(p0.y) * sinv[wid][p0.x & 7];
        float v1 = __int_as_float(p1.y) * sinv[wid][p1.x & 7];
        float v2 = __int_as_float(p2.y) * sinv[wid][p2.x & 7];
        float v3 = __int_as_float(p3.y) * sinv[wid][p3.x & 7];
        float2 z0 = __half22float2(zb0);
        float2 z1 = __half22float2(zb1);
        float2 z2 = __half22float2(zb2);
        float2 z3 = __half22float2(zb3);
        a0 += v0 * z0.x + v1 * z1.x + v2 * z2.x + v3 * z3.x;
        a1 += v0 * z0.y + v1 * z1.y + v2 * z2.y + v3 * z3.y;
    }
    for (; i < end; i++) {
        int2 p0 = g_ep[i];
        __half2 zb0 = *(const __half2*)&g_z[(size_t)p0.x * 64 + lid * 2];
        float v0 = __int_as_float(p0.y) * sinv[wid][p0.x & 7];
        float2 z0 = __half22float2(zb0);
        a0 += v0 * z0.x;
        a1 += v0 * z0.y;
    }

    float2 o = *(float2*)&out[node * DD + lid * 2];
    o.x = fmaxf(o.x + a0, 0.f);
    o.y = fmaxf(o.y + a1, 0.f);
    *(float2*)&out[node * DD + lid * 2] = o;
}

// ---------------------------------------------------------------------------
// Host-side stream/event resources (created once at load; NO device memory).
namespace {
struct Aux {
    cudaStream_t s2;
    cudaEvent_t fork_ev, join_ev;
    Aux() {
        cudaStreamCreateWithFlags(&s2, cudaStreamNonBlocking);
        cudaEventCreateWithFlags(&fork_ev, cudaEventDisableTiming);
        cudaEventCreateWithFlags(&join_ev, cudaEventDisableTiming);
    }
};
Aux g_aux;
}

extern "C" void kernel_launch(void* const* d_in, const int* in_sizes, int n_in,
                              void* d_out, int out_size) {
    const float* x      = (const float*)d_in[0];
    const int*   e_src  = (const int*)d_in[1];
    const int*   e_dst  = (const int*)d_in[2];
    const int*   e_rel  = (const int*)d_in[3];
    const float* e_w    = (const float*)d_in[4];
    const float* W_lin  = (const float*)d_in[5];
    const float* b_lin  = (const float*)d_in[6];
    const float* W_self = (const float*)d_in[7];
    const float* b_self = (const float*)d_in[8];
    float* out = (float*)d_out;

    cudaFuncSetAttribute(gemm_kernel, cudaFuncAttributeMaxDynamicSharedMemorySize, SMEM_TOTAL);

    const int SCAN_BLKS = (NN + 1023) / 1024;   // 49

    // Fork: CSR chain on s2, GEMM chain on main stream; join before gather.
    cudaEventRecord(g_aux.fork_ev, 0);
    cudaStreamWaitEvent(g_aux.s2, g_aux.fork_ev, 0);

    zero_cnt_kernel<<<(NN + 255) / 256, 256, 0, g_aux.s2>>>();
    hist_kernel<<<(NE + 255) / 256, 256, 0, g_aux.s2>>>(e_dst);
    scan1_kernel<<<SCAN_BLKS, 1024, 0, g_aux.s2>>>();
    scan2_kernel<<<1, 64, 0, g_aux.s2>>>(SCAN_BLKS);
    scan3_kernel<<<SCAN_BLKS, 1024, 0, g_aux.s2>>>();
    fill_kernel<<<(NE + 255) / 256, 256, 0, g_aux.s2>>>(e_src, e_dst, e_rel, e_w);
    cudaEventRecord(g_aux.join_ev, g_aux.s2);

    prep_w_kernel<<<(18432 + 255) / 256, 256>>>(W_lin, W_self);
    gemm_kernel<<<(NN + 127) / 128, 256, SMEM_TOTAL>>>(x, b_lin, b_self, out);

    cudaStreamWaitEvent(0, g_aux.join_ev, 0);
    gather_kernel<<<NN / 8, 256>>>(out);
}

// round 10
// speedup vs baseline: 1.6487x; 1.0278x over previous
#include <cuda_runtime.h>
#include <cuda_fp16.h>
#include <cstdint>

#define NN 50000
#define NE 1000000
#define DD 64
#define RR 8
#define ZC 512

// Scratch (allocation-free rule)
__device__ __half g_z[(size_t)NN * ZC];        // 51.2 MB fp16
__device__ uint32_t g_Wf[9 * 4 * 4 * 32 * 4];  // fp16 B fragments (73728 B)
__device__ float g_deg[NN * RR];
__device__ int  g_cnt[NN];
__device__ int  g_rs[NN];       // scan result; advanced to segment END by fill
__device__ int  g_part[64];
__device__ int2 g_ep[NE];       // packed: {src*8+rel, ew bits (pre-normalized)}

// ---------------------------------------------------------------------------
__device__ __forceinline__ uint32_t smem_u32(const void* p) {
    uint32_t a;
    asm("{ .reg .u64 t; cvta.to.shared.u64 t, %1; cvt.u32.u64 %0, t; }" : "=r"(a) : "l"(p));
    return a;
}
__device__ __forceinline__ void ldsm_x4(uint32_t* r, uint32_t addr) {
    asm volatile("ldmatrix.sync.aligned.m8n8.x4.shared.b16 {%0,%1,%2,%3}, [%4];"
                 : "=r"(r[0]), "=r"(r[1]), "=r"(r[2]), "=r"(r[3]) : "r"(addr));
}
__device__ __forceinline__ void mma_f16(float* c, const uint32_t* a, uint32_t b0, uint32_t b1) {
    asm volatile("mma.sync.aligned.m16n8k16.row.col.f32.f16.f16.f32 "
                 "{%0,%1,%2,%3}, {%4,%5,%6,%7}, {%8,%9}, {%0,%1,%2,%3};"
                 : "+f"(c[0]), "+f"(c[1]), "+f"(c[2]), "+f"(c[3])
                 : "r"(a[0]), "r"(a[1]), "r"(a[2]), "r"(a[3]), "r"(b0), "r"(b1));
}
__device__ __forceinline__ int warp_iscan(int v, int lane) {
#pragma unroll
    for (int off = 1; off < 32; off <<= 1) {
        int t = __shfl_up_sync(0xFFFFFFFFu, v, off);
        if (lane >= off) v += t;
    }
    return v;
}

// ---------------------------------------------------------------------------
// B fragments in per-lane mma layout (fp16).
__global__ void prep_w_kernel(const float* __restrict__ Wlin, const float* __restrict__ Wself) {
    int i = blockIdx.x * blockDim.x + threadIdx.x;     // 18432
    if (i >= 9 * 4 * 4 * 32 * 4) return;
    int c = i & 3, lane = (i >> 2) & 31, q = (i >> 7) & 3, kk = (i >> 9) & 3, g = i >> 11;
    int nt = q * 2 + (c >> 1);
    int k  = kk * 16 + (lane & 3) * 2 + (c & 1) * 8;
    int j  = nt * 8 + (lane >> 2);
    float v0, v1;
    if (g < 8) { int row = g * 64 + k; v0 = Wlin[row * 64 + j]; v1 = Wlin[(row + 1) * 64 + j]; }
    else       { v0 = Wself[k * 64 + j]; v1 = Wself[(k + 1) * 64 + j]; }
    __half h0 = __float2half_rn(v0), h1 = __float2half_rn(v1);
    g_Wf[i] = (uint32_t)__half_as_ushort(h0) | ((uint32_t)__half_as_ushort(h1) << 16);
}

// ---------------------------------------------------------------------------
// CSR build (runs on side stream, hidden under GEMM chain)
__global__ void zero_kernel() {
    int i = blockIdx.x * blockDim.x + threadIdx.x;
    if (i < NN) g_cnt[i] = 0;
    if (i < NN * RR) g_deg[i] = 0.f;
}
// histogram + per-(dst,rel) degree in one pass
__global__ void hist_kernel(const int* __restrict__ dst, const int* __restrict__ rel,
                            const float* __restrict__ w) {
    int e = blockIdx.x * blockDim.x + threadIdx.x;
    if (e >= NE) return;
    int d = dst[e];
    atomicAdd(&g_cnt[d], 1);
    atomicAdd(&g_deg[d * RR + rel[e]], w[e]);
}
__global__ void scan1_kernel() {
    __shared__ int wsum[32];
    int tid = threadIdx.x, lane = tid & 31, wid = tid >> 5;
    int i = blockIdx.x * 1024 + tid;
    int v = (i < NN) ? g_cnt[i] : 0;
    int s = warp_iscan(v, lane);
    if (lane == 31) wsum[wid] = s;
    __syncthreads();
    if (wid == 0) {
        int t = wsum[lane];
        int sc = warp_iscan(t, lane);
        wsum[lane] = sc - t;
    }
    __syncthreads();
    int incl = s + wsum[wid];
    if (i < NN) g_rs[i] = incl - v;
    if (tid == 1023) g_part[blockIdx.x] = incl;
}
__global__ void scan2_kernel(int nblk) {
    __shared__ int w0tot;
    int tid = threadIdx.x, lane = tid & 31, wid = tid >> 5;
    int v = (tid < nblk) ? g_part[tid] : 0;
    int s = warp_iscan(v, lane);
    if (wid == 0 && lane == 31) w0tot = s;
    __syncthreads();
    if (wid == 1) s += w0tot;
    if (tid < nblk) g_part[tid] = s - v;
}
__global__ void scan3_kernel() {
    int tid = threadIdx.x;
    int i = blockIdx.x * 1024 + tid;
    if (i < NN) g_rs[i] += g_part[blockIdx.x];
}
// fill stores PRE-NORMALIZED edge weight: ew = w / deg[dst*8+rel]
__global__ void fill_kernel(const int* __restrict__ src, const int* __restrict__ dst,
                            const int* __restrict__ rel, const float* __restrict__ w) {
    int e = blockIdx.x * blockDim.x + threadIdx.x;
    if (e >= NE) return;
    int d = dst[e], r = rel[e];
    float ew = w[e] / g_deg[d * RR + r];
    int pos = atomicAdd(&g_rs[d], 1);
    g_ep[pos] = make_int2(src[e] * 8 + r, __float_as_int(ew));
}

// ---------------------------------------------------------------------------
// GEMM: A staged in smem (fp16), fragments persist; B from L1-hot fragments;
// z writeout staged through smem for full coalescing.
#define AP 72
#define SM_BIAS 0
#define SM_AH   256                           // reused as z staging after ldsm
#define SMEM_TOTAL (SM_AH + 128 * AP * 2)     // 18688 B

__global__ __launch_bounds__(256) void gemm_kernel(const float* __restrict__ x,
                                                   const float* __restrict__ b_lin,
                                                   const float* __restrict__ b_self,
                                                   float* __restrict__ out) {
    extern __shared__ char smem[];
    uint32_t sb = smem_u32(smem);
    int t = threadIdx.x, wid = t >> 5, lid = t & 31;
    int m_base = blockIdx.x * 128;

    float* bias = (float*)(smem + SM_BIAS);
    if (t < 64) bias[t] = b_lin[t] + b_self[t];

    for (int f = t; f < 128 * 32; f += 256) {
        int m = f >> 5, kp = f & 31;
        float2 v = make_float2(0.f, 0.f);
        int gm = m_base + m;
        if (gm < NN) v = *(const float2*)&x[gm * DD + kp * 2];
        *(__half2*)(smem + SM_AH + (uint32_t)(m * AP + kp * 2) * 2) = __float22half2_rn(v);
    }
    __syncthreads();

    uint32_t a[4][4];
    {
        int arow = wid * 16 + (lid & 7) + ((lid >> 3) & 1) * 8;
        int acol = (lid >> 4) * 8;
#pragma unroll
        for (int kk = 0; kk < 4; kk++)
            ldsm_x4(a[kk], sb + SM_AH + (uint32_t)(arow * AP + kk * 16 + acol) * 2);
    }

    const uint4* Wf = (const uint4*)g_Wf;
    __half* zst = (__half*)(smem + SM_AH);

    for (int g = 0; g < 9; g++) {
        float acc[8][4];
#pragma unroll
        for (int n = 0; n < 8; n++)
#pragma unroll
            for (int q = 0; q < 4; q++) acc[n][q] = 0.f;

#pragma unroll
        for (int kk = 0; kk < 4; kk++) {
            uint4 b[4];
#pragma unroll
            for (int q = 0; q < 4; q++)
                b[q] = Wf[((g * 4 + kk) * 4 + q) * 32 + lid];
#pragma unroll
            for (int n = 0; n < 8; n++) {
                uint32_t b0 = (n & 1) ? b[n >> 1].z : b[n >> 1].x;
                uint32_t b1 = (n & 1) ? b[n >> 1].w : b[n >> 1].y;
                mma_f16(acc[n], a[kk], b0, b1);
            }
        }

        int rr0 = wid * 16 + (lid >> 2);
        int rr1 = rr0 + 8;
        int c0 = (lid & 3) * 2;
        if (g < 8) {
            __syncthreads();
#pragma unroll
            for (int n = 0; n < 8; n++) {
                int col = n * 8 + c0;
                *(__half2*)&zst[rr0 * AP + col] = __float22half2_rn(make_float2(acc[n][0], acc[n][1]));
                *(__half2*)&zst[rr1 * AP + col] = __float22half2_rn(make_float2(acc[n][2], acc[n][3]));
            }
            __syncthreads();
            for (int f = t; f < 128 * 8; f += 256) {
                int row = f >> 3, ch = f & 7;
                int gm = m_base + row;
                if (gm < NN) {
                    uint4 v = *(const uint4*)&zst[row * AP + ch * 8];
                    *(uint4*)&g_z[(size_t)gm * ZC + g * 64 + ch * 8] = v;
                }
            }
        } else {
            int r0 = m_base + rr0, r1 = m_base + rr1;
#pragma unroll
            for (int n = 0; n < 8; n++) {
                int col = n * 8 + c0;
                float2 bs = *(float2*)&bias[col];
                if (r0 < NN) *(float2*)&out[r0 * DD + col] = make_float2(acc[n][0] + bs.x, acc[n][1] + bs.y);
                if (r1 < NN) *(float2*)&out[r1 * DD + col] = make_float2(acc[n][2] + bs.x, acc[n][3] + bs.y);
            }
        }
    }
}

// ---------------------------------------------------------------------------
// Gather: single streaming pass. One warp per node; per edge: int2 + 128B row.
__global__ __launch_bounds__(256) void gather_kernel(float* __restrict__ out) {
    int t = threadIdx.x, wid = t >> 5, lid = t & 31;
    int node = blockIdx.x * 8 + wid;
    int end = g_rs[node];                 // post-fill: segment end
    int beg = end - g_cnt[node];

    float a0 = 0.f, a1 = 0.f;
    int i = beg;
    for (; i + 3 < end; i += 4) {
        int2 p0 = g_ep[i], p1 = g_ep[i + 1], p2 = g_ep[i + 2], p3 = g_ep[i + 3];
        __half2 zb0 = *(const __half2*)&g_z[(size_t)p0.x * 64 + lid * 2];
        __half2 zb1 = *(const __half2*)&g_z[(size_t)p1.x * 64 + lid * 2];
        __half2 zb2 = *(const __half2*)&g_z[(size_t)p2.x * 64 + lid * 2];
        __half2 zb3 = *(const __half2*)&g_z[(size_t)p3.x * 64 + lid * 2];
        float v0 = __int_as_float(p0.y);
        float v1 = __int_as_float(p1.y);
        float v2 = __int_as_float(p2.y);
        float v3 = __int_as_float(p3.y);
        float2 z0 = __half22float2(zb0);
        float2 z1 = __half22float2(zb1);
        float2 z2 = __half22float2(zb2);
        float2 z3 = __half22float2(zb3);
        a0 += v0 * z0.x + v1 * z1.x + v2 * z2.x + v3 * z3.x;
        a1 += v0 * z0.y + v1 * z1.y + v2 * z2.y + v3 * z3.y;
    }
    for (; i < end; i++) {
        int2 p0 = g_ep[i];
        __half2 zb0 = *(const __half2*)&g_z[(size_t)p0.x * 64 + lid * 2];
        float v0 = __int_as_float(p0.y);
        float2 z0 = __half22float2(zb0);
        a0 += v0 * z0.x;
        a1 += v0 * z0.y;
    }

    float2 o = *(float2*)&out[node * DD + lid * 2];
    o.x = fmaxf(o.x + a0, 0.f);
    o.y = fmaxf(o.y + a1, 0.f);
    *(float2*)&out[node * DD + lid * 2] = o;
}

// ---------------------------------------------------------------------------
// Host-side stream/event resources (created once at load; NO device memory).
namespace {
struct Aux {
    cudaStream_t s2;
    cudaEvent_t fork_ev, join_ev;
    Aux() {
        cudaStreamCreateWithFlags(&s2, cudaStreamNonBlocking);
        cudaEventCreateWithFlags(&fork_ev, cudaEventDisableTiming);
        cudaEventCreateWithFlags(&join_ev, cudaEventDisableTiming);
    }
};
Aux g_aux;
}

extern "C" void kernel_launch(void* const* d_in, const int* in_sizes, int n_in,
                              void* d_out, int out_size) {
    const float* x      = (const float*)d_in[0];
    const int*   e_src  = (const int*)d_in[1];
    const int*   e_dst  = (const int*)d_in[2];
    const int*   e_rel  = (const int*)d_in[3];
    const float* e_w    = (const float*)d_in[4];
    const float* W_lin  = (const float*)d_in[5];
    const float* b_lin  = (const float*)d_in[6];
    const float* W_self = (const float*)d_in[7];
    const float* b_self = (const float*)d_in[8];
    float* out = (float*)d_out;

    cudaFuncSetAttribute(gemm_kernel, cudaFuncAttributeMaxDynamicSharedMemorySize, SMEM_TOTAL);

    const int SCAN_BLKS = (NN + 1023) / 1024;   // 49

    // Fork: CSR chain on s2, GEMM chain on main stream; join before gather.
    cudaEventRecord(g_aux.fork_ev, 0);
    cudaStreamWaitEvent(g_aux.s2, g_aux.fork_ev, 0);

    zero_kernel<<<(NN * RR + 255) / 256, 256, 0, g_aux.s2>>>();
    hist_kernel<<<(NE + 255) / 256, 256, 0, g_aux.s2>>>(e_dst, e_rel, e_w);
    scan1_kernel<<<SCAN_BLKS, 1024, 0, g_aux.s2>>>();
    scan2_kernel<<<1, 64, 0, g_aux.s2>>>(SCAN_BLKS);
    scan3_kernel<<<SCAN_BLKS, 1024, 0, g_aux.s2>>>();
    fill_kernel<<<(NE + 255) / 256, 256, 0, g_aux.s2>>>(e_src, e_dst, e_rel, e_w);
    cudaEventRecord(g_aux.join_ev, g_aux.s2);

    prep_w_kernel<<<(18432 + 255) / 256, 256>>>(W_lin, W_self);
    gemm_kernel<<<(NN + 127) / 128, 256, SMEM_TOTAL>>>(x, b_lin, b_self, out);

    cudaStreamWaitEvent(0, g_aux.join_ev, 0);
    gather_kernel<<<NN / 8, 256>>>(out);
}

// round 11
// speedup vs baseline: 1.7747x; 1.0764x over previous
#include <cuda_runtime.h>
#include <cuda_fp16.h>
#include <cstdint>

#define NN 50000
#define NE 1000000
#define DD 64
#define RR 8
#define ZC 512

// Scratch (allocation-free rule)
__device__ __half g_z[(size_t)NN * ZC];        // 51.2 MB fp16
__device__ uint32_t g_Wf[9 * 4 * 4 * 32 * 4];  // fp16 B fragments (73728 B)
__device__ float g_deg[NN * RR];
__device__ int  g_cnt[NN];
__device__ int  g_rs[NN];       // scan result; advanced to segment END by fill
__device__ int  g_part[64];
__device__ int2 g_ep[NE];       // packed: {src*8+rel, ew bits (pre-normalized)}

// ---------------------------------------------------------------------------
__device__ __forceinline__ uint32_t smem_u32(const void* p) {
    uint32_t a;
    asm("{ .reg .u64 t; cvta.to.shared.u64 t, %1; cvt.u32.u64 %0, t; }" : "=r"(a) : "l"(p));
    return a;
}
__device__ __forceinline__ void ldsm_x4(uint32_t* r, uint32_t addr) {
    asm volatile("ldmatrix.sync.aligned.m8n8.x4.shared.b16 {%0,%1,%2,%3}, [%4];"
                 : "=r"(r[0]), "=r"(r[1]), "=r"(r[2]), "=r"(r[3]) : "r"(addr));
}
__device__ __forceinline__ void mma_f16(float* c, const uint32_t* a, uint32_t b0, uint32_t b1) {
    asm volatile("mma.sync.aligned.m16n8k16.row.col.f32.f16.f16.f32 "
                 "{%0,%1,%2,%3}, {%4,%5,%6,%7}, {%8,%9}, {%0,%1,%2,%3};"
                 : "+f"(c[0]), "+f"(c[1]), "+f"(c[2]), "+f"(c[3])
                 : "r"(a[0]), "r"(a[1]), "r"(a[2]), "r"(a[3]), "r"(b0), "r"(b1));
}
__device__ __forceinline__ int warp_iscan(int v, int lane) {
#pragma unroll
    for (int off = 1; off < 32; off <<= 1) {
        int t = __shfl_up_sync(0xFFFFFFFFu, v, off);
        if (lane >= off) v += t;
    }
    return v;
}

// ---------------------------------------------------------------------------
__global__ void prep_w_kernel(const float* __restrict__ Wlin, const float* __restrict__ Wself) {
    int i = blockIdx.x * blockDim.x + threadIdx.x;     // 18432
    if (i >= 9 * 4 * 4 * 32 * 4) return;
    int c = i & 3, lane = (i >> 2) & 31, q = (i >> 7) & 3, kk = (i >> 9) & 3, g = i >> 11;
    int nt = q * 2 + (c >> 1);
    int k  = kk * 16 + (lane & 3) * 2 + (c & 1) * 8;
    int j  = nt * 8 + (lane >> 2);
    float v0, v1;
    if (g < 8) { int row = g * 64 + k; v0 = Wlin[row * 64 + j]; v1 = Wlin[(row + 1) * 64 + j]; }
    else       { v0 = Wself[k * 64 + j]; v1 = Wself[(k + 1) * 64 + j]; }
    __half h0 = __float2half_rn(v0), h1 = __float2half_rn(v1);
    g_Wf[i] = (uint32_t)__half_as_ushort(h0) | ((uint32_t)__half_as_ushort(h1) << 16);
}

// ---------------------------------------------------------------------------
// CSR build (side stream, hidden under GEMM chain)
__global__ void zero_kernel() {
    int i = blockIdx.x * blockDim.x + threadIdx.x;
    if (i < NN) g_cnt[i] = 0;
    if (i < NN * RR) g_deg[i] = 0.f;
}
__global__ void hist_kernel(const int* __restrict__ dst, const int* __restrict__ rel,
                            const float* __restrict__ w) {
    int e = blockIdx.x * blockDim.x + threadIdx.x;
    if (e >= NE) return;
    int d = dst[e];
    atomicAdd(&g_cnt[d], 1);
    atomicAdd(&g_deg[d * RR + rel[e]], w[e]);
}
__global__ void scan1_kernel() {
    __shared__ int wsum[32];
    int tid = threadIdx.x, lane = tid & 31, wid = tid >> 5;
    int i = blockIdx.x * 1024 + tid;
    int v = (i < NN) ? g_cnt[i] : 0;
    int s = warp_iscan(v, lane);
    if (lane == 31) wsum[wid] = s;
    __syncthreads();
    if (wid == 0) {
        int t = wsum[lane];
        int sc = warp_iscan(t, lane);
        wsum[lane] = sc - t;
    }
    __syncthreads();
    int incl = s + wsum[wid];
    if (i < NN) g_rs[i] = incl - v;
    if (tid == 1023) g_part[blockIdx.x] = incl;
}
// scan3 with scan2 inlined: every block redundantly scans the 49 partials.
__global__ void scan3_kernel(int nblk) {
    __shared__ int pex[64];
    __shared__ int w0tot;
    int tid = threadIdx.x, lane = tid & 31, wid5 = tid >> 5;
    if (tid < 64) {
        int v = (tid < nblk) ? g_part[tid] : 0;
        int s = warp_iscan(v, lane);
        if (wid5 == 0 && lane == 31) w0tot = s;
        pex[tid] = s - v;
    }
    __syncthreads();
    if (tid < 64 && wid5 == 1) pex[tid] += w0tot;
    __syncthreads();
    int i = blockIdx.x * 1024 + tid;
    if (i < NN) g_rs[i] += pex[blockIdx.x];
}
// fill stores PRE-NORMALIZED edge weight: ew = w / deg[dst*8+rel]
__global__ void fill_kernel(const int* __restrict__ src, const int* __restrict__ dst,
                            const int* __restrict__ rel, const float* __restrict__ w) {
    int e = blockIdx.x * blockDim.x + threadIdx.x;
    if (e >= NE) return;
    int d = dst[e], r = rel[e];
    float ew = w[e] / g_deg[d * RR + r];
    int pos = atomicAdd(&g_rs[d], 1);
    g_ep[pos] = make_int2(src[e] * 8 + r, __float_as_int(ew));
}

// ---------------------------------------------------------------------------
// GEMM (unchanged from R9/R10 winner)
#define AP 72
#define SM_BIAS 0
#define SM_AH   256
#define SMEM_TOTAL (SM_AH + 128 * AP * 2)     // 18688 B

__global__ __launch_bounds__(256) void gemm_kernel(const float* __restrict__ x,
                                                   const float* __restrict__ b_lin,
                                                   const float* __restrict__ b_self,
                                                   float* __restrict__ out) {
    extern __shared__ char smem[];
    uint32_t sb = smem_u32(smem);
    int t = threadIdx.x, wid = t >> 5, lid = t & 31;
    int m_base = blockIdx.x * 128;

    float* bias = (float*)(smem + SM_BIAS);
    if (t < 64) bias[t] = b_lin[t] + b_self[t];

    for (int f = t; f < 128 * 32; f += 256) {
        int m = f >> 5, kp = f & 31;
        float2 v = make_float2(0.f, 0.f);
        int gm = m_base + m;
        if (gm < NN) v = *(const float2*)&x[gm * DD + kp * 2];
        *(__half2*)(smem + SM_AH + (uint32_t)(m * AP + kp * 2) * 2) = __float22half2_rn(v);
    }
    __syncthreads();

    uint32_t a[4][4];
    {
        int arow = wid * 16 + (lid & 7) + ((lid >> 3) & 1) * 8;
        int acol = (lid >> 4) * 8;
#pragma unroll
        for (int kk = 0; kk < 4; kk++)
            ldsm_x4(a[kk], sb + SM_AH + (uint32_t)(arow * AP + kk * 16 + acol) * 2);
    }

    const uint4* Wf = (const uint4*)g_Wf;
    __half* zst = (__half*)(smem + SM_AH);

    for (int g = 0; g < 9; g++) {
        float acc[8][4];
#pragma unroll
        for (int n = 0; n < 8; n++)
#pragma unroll
            for (int q = 0; q < 4; q++) acc[n][q] = 0.f;

#pragma unroll
        for (int kk = 0; kk < 4; kk++) {
            uint4 b[4];
#pragma unroll
            for (int q = 0; q < 4; q++)
                b[q] = Wf[((g * 4 + kk) * 4 + q) * 32 + lid];
#pragma unroll
            for (int n = 0; n < 8; n++) {
                uint32_t b0 = (n & 1) ? b[n >> 1].z : b[n >> 1].x;
                uint32_t b1 = (n & 1) ? b[n >> 1].w : b[n >> 1].y;
                mma_f16(acc[n], a[kk], b0, b1);
            }
        }

        int rr0 = wid * 16 + (lid >> 2);
        int rr1 = rr0 + 8;
        int c0 = (lid & 3) * 2;
        if (g < 8) {
            __syncthreads();
#pragma unroll
            for (int n = 0; n < 8; n++) {
                int col = n * 8 + c0;
                *(__half2*)&zst[rr0 * AP + col] = __float22half2_rn(make_float2(acc[n][0], acc[n][1]));
                *(__half2*)&zst[rr1 * AP + col] = __float22half2_rn(make_float2(acc[n][2], acc[n][3]));
            }
            __syncthreads();
            for (int f = t; f < 128 * 8; f += 256) {
                int row = f >> 3, ch = f & 7;
                int gm = m_base + row;
                if (gm < NN) {
                    uint4 v = *(const uint4*)&zst[row * AP + ch * 8];
                    *(uint4*)&g_z[(size_t)gm * ZC + g * 64 + ch * 8] = v;
                }
            }
        } else {
            int r0 = m_base + rr0, r1 = m_base + rr1;
#pragma unroll
            for (int n = 0; n < 8; n++) {
                int col = n * 8 + c0;
                float2 bs = *(float2*)&bias[col];
                if (r0 < NN) *(float2*)&out[r0 * DD + col] = make_float2(acc[n][0] + bs.x, acc[n][1] + bs.y);
                if (r1 < NN) *(float2*)&out[r1 * DD + col] = make_float2(acc[n][2] + bs.x, acc[n][3] + bs.y);
            }
        }
    }
}

// ---------------------------------------------------------------------------
// Gather v2: one warp per node, half-warp per z-row.
// Each lane loads uint2 (4 halves); 16 lanes cover one 128B row -> 2 rows per
// warp load. Unroll 4 edges per half-warp = 8 rows in flight per warp.
__global__ __launch_bounds__(256) void gather_kernel(float* __restrict__ out) {
    int t = threadIdx.x, wid = t >> 5, lid = t & 31;
    int node = blockIdx.x * 8 + wid;
    int end = g_rs[node];                 // post-fill: segment end
    int beg = end - g_cnt[node];

    int half = lid >> 4;                  // 0 or 1
    int hl = lid & 15;                    // lane within half-warp; owns dims hl*4..+3

    float a0 = 0.f, a1 = 0.f, a2 = 0.f, a3 = 0.f;
    int i = beg + half;
    for (; i + 6 < end; i += 8) {         // 4 edges per half-warp per iter
        int2 p0 = g_ep[i], p1 = g_ep[i + 2], p2 = g_ep[i + 4], p3 = g_ep[i + 6];
        uint2 r0 = *(const uint2*)&g_z[(size_t)p0.x * 64 + hl * 4];
        uint2 r1 = *(const uint2*)&g_z[(size_t)p1.x * 64 + hl * 4];
        uint2 r2 = *(const uint2*)&g_z[(size_t)p2.x * 64 + hl * 4];
        uint2 r3 = *(const uint2*)&g_z[(size_t)p3.x * 64 + hl * 4];
        float v0 = __int_as_float(p0.y), v1 = __int_as_float(p1.y);
        float v2 = __int_as_float(p2.y), v3 = __int_as_float(p3.y);
        float2 f0a = __half22float2(*(__half2*)&r0.x), f0b = __half22float2(*(__half2*)&r0.y);
        float2 f1a = __half22float2(*(__half2*)&r1.x), f1b = __half22float2(*(__half2*)&r1.y);
        float2 f2a = __half22float2(*(__half2*)&r2.x), f2b = __half22float2(*(__half2*)&r2.y);
        float2 f3a = __half22float2(*(__half2*)&r3.x), f3b = __half22float2(*(__half2*)&r3.y);
        a0 += v0 * f0a.x + v1 * f1a.x + v2 * f2a.x + v3 * f3a.x;
        a1 += v0 * f0a.y + v1 * f1a.y + v2 * f2a.y + v3 * f3a.y;
        a2 += v0 * f0b.x + v1 * f1b.x + v2 * f2b.x + v3 * f3b.x;
        a3 += v0 * f0b.y + v1 * f1b.y + v2 * f2b.y + v3 * f3b.y;
    }
    for (; i < end; i += 2) {
        int2 p0 = g_ep[i];
        uint2 r0 = *(const uint2*)&g_z[(size_t)p0.x * 64 + hl * 4];
        float v0 = __int_as_float(p0.y);
        float2 f0a = __half22float2(*(__half2*)&r0.x), f0b = __half22float2(*(__half2*)&r0.y);
        a0 += v0 * f0a.x; a1 += v0 * f0a.y; a2 += v0 * f0b.x; a3 += v0 * f0b.y;
    }

    // merge the two half-warps (same dims at lane lid^16)
    a0 += __shfl_xor_sync(0xFFFFFFFFu, a0, 16);
    a1 += __shfl_xor_sync(0xFFFFFFFFu, a1, 16);
    a2 += __shfl_xor_sync(0xFFFFFFFFu, a2, 16);
    a3 += __shfl_xor_sync(0xFFFFFFFFu, a3, 16);

    if (half == 0) {
        float4 o = *(float4*)&out[node * DD + hl * 4];
        o.x = fmaxf(o.x + a0, 0.f);
        o.y = fmaxf(o.y + a1, 0.f);
        o.z = fmaxf(o.z + a2, 0.f);
        o.w = fmaxf(o.w + a3, 0.f);
        *(float4*)&out[node * DD + hl * 4] = o;
    }
}

// ---------------------------------------------------------------------------
// Host-side stream/event resources (created once at load; NO device memory).
namespace {
struct Aux {
    cudaStream_t s2;
    cudaEvent_t fork_ev, join_ev;
    Aux() {
        cudaStreamCreateWithFlags(&s2, cudaStreamNonBlocking);
        cudaEventCreateWithFlags(&fork_ev, cudaEventDisableTiming);
        cudaEventCreateWithFlags(&join_ev, cudaEventDisableTiming);
    }
};
Aux g_aux;
}

extern "C" void kernel_launch(void* const* d_in, const int* in_sizes, int n_in,
                              void* d_out, int out_size) {
    const float* x      = (const float*)d_in[0];
    const int*   e_src  = (const int*)d_in[1];
    const int*   e_dst  = (const int*)d_in[2];
    const int*   e_rel  = (const int*)d_in[3];
    const float* e_w    = (const float*)d_in[4];
    const float* W_lin  = (const float*)d_in[5];
    const float* b_lin  = (const float*)d_in[6];
    const float* W_self = (const float*)d_in[7];
    const float* b_self = (const float*)d_in[8];
    float* out = (float*)d_out;

    cudaFuncSetAttribute(gemm_kernel, cudaFuncAttributeMaxDynamicSharedMemorySize, SMEM_TOTAL);

    const int SCAN_BLKS = (NN + 1023) / 1024;   // 49

    // Fork: CSR chain on s2, GEMM chain on main stream; join before gather.
    cudaEventRecord(g_aux.fork_ev, 0);
    cudaStreamWaitEvent(g_aux.s2, g_aux.fork_ev, 0);

    zero_kernel<<<(NN * RR + 255) / 256, 256, 0, g_aux.s2>>>();
    hist_kernel<<<(NE + 255) / 256, 256, 0, g_aux.s2>>>(e_dst, e_rel, e_w);
    scan1_kernel<<<SCAN_BLKS, 1024, 0, g_aux.s2>>>();
    scan3_kernel<<<SCAN_BLKS, 1024, 0, g_aux.s2>>>(SCAN_BLKS);
    fill_kernel<<<(NE + 255) / 256, 256, 0, g_aux.s2>>>(e_src, e_dst, e_rel, e_w);
    cudaEventRecord(g_aux.join_ev, g_aux.s2);

    prep_w_kernel<<<(18432 + 255) / 256, 256>>>(W_lin, W_self);
    gemm_kernel<<<(NN + 127) / 128, 256, SMEM_TOTAL>>>(x, b_lin, b_self, out);

    cudaStreamWaitEvent(0, g_aux.join_ev, 0);
    gather_kernel<<<NN / 8, 256>>>(out);
}